// round 1
// baseline (speedup 1.0000x reference)
#include <cuda_runtime.h>
#include <cstdint>

// Problem constants
#define T_ROWS   786432
#define NN       50        // inner dim of GEMM1
#define KK       400       // hidden features
#define CC       10        // classes
#define JPOOL    24        // pooling window
#define NSEG     (T_ROWS / JPOOL)      // 32768

// Tiling
#define CHUNK_ROWS 48                  // 2 whole segments per chunk
#define SEGS_PER_CHUNK (CHUNK_ROWS / JPOOL)   // 2
#define NCHUNKS  (T_ROWS / CHUNK_ROWS)        // 16384
#define KG 16        // k-groups (threadIdx.x & 15)
#define JG 12        // j-groups
#define TK 5         // k per thread per pass
#define TJ 4         // rows per thread
#define NPASS (KK / (KG * TK))   // 5
#define NTHREADS (KG * JG)       // 192
#define W1_STRIDE 51             // pad 50 -> 51 for conflict-free column reads
#define GRID_BLOCKS 304          // ~2 per SM (152 SMs on GB300)

// Shared memory layout (floats):
//   w1_s : KK * W1_STRIDE            = 20400
//   w2_s : CC * KK                   =  4000
//   x_s  : CHUNK_ROWS * NN           =  2400
//   feat : SEGS_PER_CHUNK * KK       =   800
// total = 27600 floats = 110400 bytes
#define SMEM_FLOATS (KK * W1_STRIDE + CC * KK + CHUNK_ROWS * NN + SEGS_PER_CHUNK * KK)

__global__ void __launch_bounds__(NTHREADS, 2)
classifier_fused_kernel(const float* __restrict__ x,
                        const float* __restrict__ W1,
                        const float* __restrict__ W2,
                        float* __restrict__ out)
{
    extern __shared__ float smem[];
    float* w1_s = smem;                          // [KK][W1_STRIDE]
    float* w2_s = w1_s + KK * W1_STRIDE;         // [CC][KK]
    float* x_s  = w2_s + CC * KK;                // [CHUNK_ROWS][NN]
    float* feat = x_s + CHUNK_ROWS * NN;         // [SEGS_PER_CHUNK][KK]

    const int tid = threadIdx.x;

    // ---- one-time loads: W1 (padded) and W2 into shared ----
    for (int i = tid; i < KK * NN; i += NTHREADS) {
        int r = i / NN;
        int n = i - r * NN;
        w1_s[r * W1_STRIDE + n] = W1[i];
    }
    for (int i = tid; i < CC * KK; i += NTHREADS) {
        w2_s[i] = W2[i];
    }

    const int kg = tid & (KG - 1);   // 0..15
    const int jg = tid >> 4;         // 0..11
    const int row_local = jg * TJ;               // 0..44, TJ divides JPOOL
    const int seg_local = row_local / JPOOL;     // 0 or 1 (all TJ rows same segment)

    for (int chunk = blockIdx.x; chunk < NCHUNKS; chunk += gridDim.x) {
        __syncthreads();  // previous iteration's feat readers / x readers done

        // zero pooled-feature accumulator
        for (int i = tid; i < SEGS_PER_CHUNK * KK; i += NTHREADS) feat[i] = 0.0f;

        // load x chunk: 2400 contiguous floats, vectorized float4
        {
            const float4* xg = reinterpret_cast<const float4*>(
                x + (size_t)chunk * (CHUNK_ROWS * NN));
            float4* xs4 = reinterpret_cast<float4*>(x_s);
            #pragma unroll
            for (int i = tid; i < (CHUNK_ROWS * NN) / 4; i += NTHREADS) {
                xs4[i] = xg[i];
            }
        }
        __syncthreads();

        const float* xrow0 = x_s + row_local * NN;

        #pragma unroll 1
        for (int pass = 0; pass < NPASS; pass++) {
            const int k0 = pass * (KG * TK) + kg * TK;
            const float* wbase = w1_s + k0 * W1_STRIDE;

            float acc[TJ][TK];
            #pragma unroll
            for (int j = 0; j < TJ; j++)
                #pragma unroll
                for (int t = 0; t < TK; t++) acc[j][t] = 0.0f;

            #pragma unroll 2
            for (int n = 0; n < NN; n++) {
                float xv[TJ];
                #pragma unroll
                for (int j = 0; j < TJ; j++) xv[j] = xrow0[j * NN + n];
                float wv[TK];
                #pragma unroll
                for (int t = 0; t < TK; t++) wv[t] = wbase[t * W1_STRIDE + n];
                #pragma unroll
                for (int j = 0; j < TJ; j++)
                    #pragma unroll
                    for (int t = 0; t < TK; t++)
                        acc[j][t] = fmaf(xv[j], wv[t], acc[j][t]);
            }

            // relu per (row,k), pool over this thread's TJ rows (same segment)
            #pragma unroll
            for (int t = 0; t < TK; t++) {
                float s = fmaxf(acc[0][t], 0.0f);
                #pragma unroll
                for (int j = 1; j < TJ; j++) s += fmaxf(acc[j][t], 0.0f);
                atomicAdd(&feat[seg_local * KK + k0 + t], s);
            }
        }
        __syncthreads();

        // ---- fused GEMM2: 20 outputs (2 segments x 10 classes) ----
        // 160 threads: group g = tid/8 -> (seg, class); 8 lanes reduce over K
        if (tid < 160) {
            const int g = tid >> 3;        // 0..19
            const int l = tid & 7;         // 0..7
            const int s = g / CC;          // 0 or 1
            const int c = g - s * CC;      // 0..9
            const float* frow = feat + s * KK;
            const float* wrow = w2_s + c * KK;
            float v = 0.0f;
            #pragma unroll
            for (int k = l; k < KK; k += 8) v = fmaf(frow[k], wrow[k], v);
            v += __shfl_down_sync(0xffffffffu, v, 4, 8);
            v += __shfl_down_sync(0xffffffffu, v, 2, 8);
            v += __shfl_down_sync(0xffffffffu, v, 1, 8);
            if (l == 0) {
                out[(size_t)(chunk * SEGS_PER_CHUNK + s) * CC + c] =
                    v * (1.0f / (float)JPOOL);
            }
        }
    }
}

extern "C" void kernel_launch(void* const* d_in, const int* in_sizes, int n_in,
                              void* d_out, int out_size)
{
    const float* x  = (const float*)d_in[0];
    const float* W1 = (const float*)d_in[1];
    const float* W2 = (const float*)d_in[2];
    float* out = (float*)d_out;

    const int smem_bytes = SMEM_FLOATS * (int)sizeof(float);
    cudaFuncSetAttribute(classifier_fused_kernel,
                         cudaFuncAttributeMaxDynamicSharedMemorySize, smem_bytes);

    classifier_fused_kernel<<<GRID_BLOCKS, NTHREADS, smem_bytes>>>(x, W1, W2, out);
}

// round 4
// speedup vs baseline: 1.3989x; 1.3989x over previous
#include <cuda_runtime.h>
#include <cuda_fp16.h>
#include <cstdint>

// ---------------- problem constants ----------------
#define T_ROWS   786432
#define NIN      50          // GEMM1 reduction dim (padded to 64 in smem)
#define KFEAT    400         // hidden features
#define CC       10          // classes
#define JP       24          // pooling window
#define SC_ROWS  384         // superchunk rows = 16 segments = 24 m16-tiles
#define SEGS     16
#define NSC      (T_ROWS / SC_ROWS)      // 2048
#define NTHREADS 256
#define NWARPS   8
#define MT_PER_WARP 3                    // 24 m-tiles / 8 warps -> rows [48w,48w+48) = segs {2w,2w+1}
#define NTILES_N 50                      // 400 / 8
#define GRID     152

// ---------------- smem layout (bytes) ----------------
// A: 384 rows x 64 fp16 (128 B/row, swizzled)  = 49152
// B: 400 rows x 64 fp16 (128 B/row, swizzled)  = 51200
// feat: 16 x 400 fp32                           = 25600
// W2: 10 x 400 fp32                             = 16000
#define A_OFF      0
#define A_BYTES    (SC_ROWS * 128)
#define B_OFF      (A_OFF + A_BYTES)
#define B_BYTES    (KFEAT * 128)
#define FEAT_OFF   (B_OFF + B_BYTES)
#define FEAT_BYTES (SEGS * KFEAT * 4)
#define W2_OFF     (FEAT_OFF + FEAT_BYTES)
#define W2_BYTES   (CC * KFEAT * 4)
#define SMEM_TOTAL (W2_OFF + W2_BYTES)   // 141952

__device__ __forceinline__ uint32_t smem_u32(const void* p) {
    uint32_t a;
    asm("{ .reg .u64 t; cvta.to.shared.u64 t, %1; cvt.u32.u64 %0, t; }" : "=r"(a) : "l"(p));
    return a;
}

// swizzled byte offset for element (row, k) in a [rows x 64] fp16 tile:
// 16B chunk c = k>>3, swizzled c' = c ^ (row & 7)
__device__ __forceinline__ uint32_t swz_off(int row, int kpair /* k = 2*kpair */) {
    uint32_t bytecol = (uint32_t)(4 * kpair);
    return (uint32_t)row * 128u + (((bytecol >> 4) ^ (uint32_t)(row & 7)) << 4) + (bytecol & 15u);
}

__global__ void __launch_bounds__(NTHREADS, 1)
classifier_mma_kernel(const float* __restrict__ x,
                      const float* __restrict__ W1,
                      const float* __restrict__ W2,
                      float* __restrict__ out)
{
    extern __shared__ char smem[];
    float* feat = (float*)(smem + FEAT_OFF);
    float* w2s  = (float*)(smem + W2_OFF);

    const int tid  = threadIdx.x;
    const int wid  = tid >> 5;
    const int lane = tid & 31;
    const uint32_t sbase = smem_u32(smem);

    // ---- zero A & B (covers K padding 50..63) ----
    for (int i = tid; i < (A_BYTES + B_BYTES) / 4; i += NTHREADS)
        ((uint32_t*)smem)[i] = 0;
    __syncthreads();

    // ---- load W1 -> B smem (fp16, swizzled); W2 -> smem fp32 ----
    for (int i = tid; i < KFEAT * 25; i += NTHREADS) {
        int f = i / 25, p = i - f * 25;
        float2 v = *(const float2*)(W1 + f * NIN + 2 * p);
        *(half2*)(smem + B_OFF + swz_off(f, p)) = __float22half2_rn(v);
    }
    for (int i = tid; i < CC * KFEAT; i += NTHREADS) w2s[i] = W2[i];

    // ---- per-lane invariant ldmatrix address pieces ----
    const int rrA = lane & 15;          // A row within tile
    const int chi = lane >> 4;          // A chunk-half selector (0/1)
    const int nl  = lane & 7;           // B row-in-tile
    const int blk = lane >> 3;          // B block index (0..3)
    // B addrs: row = n0 + nl, (row&7)==nl since n0 % 8 == 0
    const uint32_t bAddr0 = sbase + B_OFF + (uint32_t)nl * 128 + (((uint32_t)(blk ^ nl)) << 4);
    const uint32_t bAddr1 = sbase + B_OFF + (uint32_t)nl * 128 + (((uint32_t)((blk + 4) ^ nl)) << 4);
    const int  tig    = lane & 3;
    const bool leader = (lane < 4);

    for (int sc = blockIdx.x; sc < NSC; sc += GRID) {
        __syncthreads();   // prev mma A-readers + gemm2 feat-readers done

        // zero pooled-feature accumulator
        for (int i = tid; i < SEGS * KFEAT; i += NTHREADS) feat[i] = 0.0f;

        // load x superchunk -> A smem (fp16, swizzled)
        {
            const size_t rg0 = (size_t)sc * SC_ROWS;
            #pragma unroll 1
            for (int i = tid; i < SC_ROWS * 25; i += NTHREADS) {
                int r = i / 25, p = i - r * 25;
                float2 v = *(const float2*)(x + (rg0 + r) * NIN + 2 * p);
                *(half2*)(smem + A_OFF + swz_off(r, p)) = __float22half2_rn(v);
            }
        }
        __syncthreads();

        // ---- GEMM1 + relu + pool (each warp: 3 m-tiles = exactly segs 2w, 2w+1) ----
        #pragma unroll 1
        for (int i = 0; i < MT_PER_WARP; i++) {
            const int mt   = wid * MT_PER_WARP + i;
            const int row0 = mt * 16;
            const int seg_lo = row0 / JP;
            const int seg_hi = (row0 + 8) / JP;
            float* flo = feat + seg_lo * KFEAT;
            float* fhi = feat + seg_hi * KFEAT;
            const bool same_seg = (seg_lo == seg_hi);

            // A fragments for all 4 k-steps (reused across 50 n-tiles)
            uint32_t a[4][4];
            #pragma unroll
            for (int ks = 0; ks < 4; ks++) {
                uint32_t addr = sbase + A_OFF + (uint32_t)(row0 + rrA) * 128
                              + (((uint32_t)((2 * ks + chi) ^ (rrA & 7))) << 4);
                asm volatile("ldmatrix.sync.aligned.m8n8.x4.shared.b16 {%0,%1,%2,%3}, [%4];"
                             : "=r"(a[ks][0]), "=r"(a[ks][1]), "=r"(a[ks][2]), "=r"(a[ks][3])
                             : "r"(addr));
            }

            uint32_t ba0 = bAddr0, ba1 = bAddr1;
            #pragma unroll 2
            for (int nt = 0; nt < NTILES_N; nt++) {
                uint32_t b[8];
                asm volatile("ldmatrix.sync.aligned.m8n8.x4.shared.b16 {%0,%1,%2,%3}, [%4];"
                             : "=r"(b[0]), "=r"(b[1]), "=r"(b[2]), "=r"(b[3]) : "r"(ba0));
                asm volatile("ldmatrix.sync.aligned.m8n8.x4.shared.b16 {%0,%1,%2,%3}, [%4];"
                             : "=r"(b[4]), "=r"(b[5]), "=r"(b[6]), "=r"(b[7]) : "r"(ba1));
                ba0 += 1024; ba1 += 1024;   // next 8 B-rows

                float c0 = 0.f, c1 = 0.f, c2 = 0.f, c3 = 0.f;
                #pragma unroll
                for (int ks = 0; ks < 4; ks++) {
                    asm volatile(
                        "mma.sync.aligned.m16n8k16.row.col.f32.f16.f16.f32 "
                        "{%0,%1,%2,%3}, {%4,%5,%6,%7}, {%8,%9}, {%0,%1,%2,%3};"
                        : "+f"(c0), "+f"(c1), "+f"(c2), "+f"(c3)
                        : "r"(a[ks][0]), "r"(a[ks][1]), "r"(a[ks][2]), "r"(a[ks][3]),
                          "r"(b[2 * ks]), "r"(b[2 * ks + 1]));
                }

                // relu, then sum over the 8 lane-rows (bits 2..4 of lane)
                c0 = fmaxf(c0, 0.f); c1 = fmaxf(c1, 0.f);
                c2 = fmaxf(c2, 0.f); c3 = fmaxf(c3, 0.f);
                #pragma unroll
                for (int m = 4; m <= 16; m <<= 1) {
                    c0 += __shfl_xor_sync(0xffffffffu, c0, m);
                    c1 += __shfl_xor_sync(0xffffffffu, c1, m);
                    c2 += __shfl_xor_sync(0xffffffffu, c2, m);
                    c3 += __shfl_xor_sync(0xffffffffu, c3, m);
                }
                if (leader) {
                    const int col = nt * 8 + 2 * tig;
                    if (same_seg) {
                        flo[col]     += c0 + c2;
                        flo[col + 1] += c1 + c3;
                    } else {
                        flo[col]     += c0;
                        flo[col + 1] += c1;
                        fhi[col]     += c2;
                        fhi[col + 1] += c3;
                    }
                }
            }
        }
        __syncthreads();   // all pooled sums in feat

        // ---- fused GEMM2: 160 outputs (16 segs x 10 classes) ----
        if (tid < SEGS * CC) {
            const int seg = tid / CC;
            const int c   = tid - seg * CC;
            const float4* f4 = (const float4*)(feat + seg * KFEAT);
            const float4* g4 = (const float4*)(w2s + c * KFEAT);
            float acc = 0.0f;
            #pragma unroll 4
            for (int k = 0; k < KFEAT / 4; k++) {
                float4 fa = f4[k], gb = g4[k];
                acc = fmaf(fa.x, gb.x, acc);
                acc = fmaf(fa.y, gb.y, acc);
                acc = fmaf(fa.z, gb.z, acc);
                acc = fmaf(fa.w, gb.w, acc);
            }
            out[(size_t)(sc * SEGS + seg) * CC + c] = acc * (1.0f / (float)JP);
        }
        // loop-top __syncthreads covers feat/A reuse
    }
}

extern "C" void kernel_launch(void* const* d_in, const int* in_sizes, int n_in,
                              void* d_out, int out_size)
{
    const float* x  = (const float*)d_in[0];
    const float* W1 = (const float*)d_in[1];
    const float* W2 = (const float*)d_in[2];
    float* out = (float*)d_out;

    cudaFuncSetAttribute(classifier_mma_kernel,
                         cudaFuncAttributeMaxDynamicSharedMemorySize, SMEM_TOTAL);
    classifier_mma_kernel<<<GRID, NTHREADS, SMEM_TOTAL>>>(x, W1, W2, out);
}

// round 5
// speedup vs baseline: 3.5070x; 2.5070x over previous
#include <cuda_runtime.h>
#include <cuda_fp16.h>
#include <cstdint>

// ---------------- problem constants ----------------
#define T_ROWS   786432
#define NIN      50          // GEMM1 reduction dim (padded to 64 in smem)
#define KFEAT    400         // hidden features = 25 m16 feature-tiles
#define CC       10          // classes
#define JP       24          // pooling window = 3 n8-tiles
#define SC_ROWS  384         // superchunk rows = 16 segments
#define SEGS     16
#define NSC      (T_ROWS / SC_ROWS)      // 2048
#define NTHREADS 640
#define NWARPS   20          // 5 ftile-groups x 4 seg-groups
#define FT_PER_W 5           // 25 ftiles / 5 groups
#define SEG_PER_W 4          // 16 segs / 4 groups
#define GRID     152

// ---------------- smem layout (bytes) ----------------
// X (B operand): 384 rows x 64 fp16 (128 B/row, swizzled) = 49152
// W1 (A operand): 400 rows x 64 fp16 (swizzled)           = 51200
// feat: 16 x 400 fp32                                      = 25600
// W2:   10 x 400 fp32                                      = 16000
#define X_OFF      0
#define X_BYTES    (SC_ROWS * 128)
#define W1_OFF     (X_OFF + X_BYTES)
#define W1_BYTES   (KFEAT * 128)
#define FEAT_OFF   (W1_OFF + W1_BYTES)
#define FEAT_BYTES (SEGS * KFEAT * 4)
#define W2_OFF     (FEAT_OFF + FEAT_BYTES)
#define W2_BYTES   (CC * KFEAT * 4)
#define SMEM_TOTAL (W2_OFF + W2_BYTES)   // 141952

__device__ __forceinline__ uint32_t smem_u32(const void* p) {
    uint32_t a;
    asm("{ .reg .u64 t; cvta.to.shared.u64 t, %1; cvt.u32.u64 %0, t; }" : "=r"(a) : "l"(p));
    return a;
}

// swizzled byte offset for element (row, k) in a [rows x 64] fp16 tile
__device__ __forceinline__ uint32_t swz_off(int row, int kpair /* k = 2*kpair */) {
    uint32_t bytecol = (uint32_t)(4 * kpair);
    return (uint32_t)row * 128u + (((bytecol >> 4) ^ (uint32_t)(row & 7)) << 4) + (bytecol & 15u);
}

__global__ void __launch_bounds__(NTHREADS, 1)
classifier_mma2_kernel(const float* __restrict__ x,
                       const float* __restrict__ W1,
                       const float* __restrict__ W2,
                       float* __restrict__ out)
{
    extern __shared__ char smem[];
    float* feat = (float*)(smem + FEAT_OFF);
    float* w2s  = (float*)(smem + W2_OFF);

    const int tid  = threadIdx.x;
    const int wid  = tid >> 5;
    const int lane = tid & 31;
    const uint32_t sbase = smem_u32(smem);

    // ---- zero X & W1 smem (covers K padding 50..63) ----
    for (int i = tid; i < (X_BYTES + W1_BYTES) / 4; i += NTHREADS)
        ((uint32_t*)smem)[i] = 0;
    __syncthreads();

    // ---- load W1 -> smem (fp16, swizzled); W2 -> smem fp32 ----
    for (int i = tid; i < KFEAT * 25; i += NTHREADS) {
        int f = i / 25, p = i - f * 25;
        float2 v = *(const float2*)(W1 + f * NIN + 2 * p);
        *(half2*)(smem + W1_OFF + swz_off(f, p)) = __float22half2_rn(v);
    }
    for (int i = tid; i < CC * KFEAT; i += NTHREADS) w2s[i] = W2[i];

    // ---- per-lane invariant ldmatrix address pieces ----
    const int rrA = lane & 15;          // A (W1) row within ftile
    const int chi = lane >> 4;          // A chunk-half selector
    const int nl  = lane & 7;           // B (x) row-in-ntile
    const int blk = lane >> 3;          // B chunk index (0..3)
    const int g   = lane >> 2;          // feature row-group within ftile
    const int tig = lane & 3;

    const int wr = wid / 5;             // seg-group 0..3
    const int wc = wid - wr * 5;        // ftile-group 0..4

    for (int sc = blockIdx.x; sc < NSC; sc += GRID) {
        __syncthreads();   // prev mma X-readers + gemm2 feat-readers done

        // load x superchunk -> X smem (fp16, swizzled)
        {
            const size_t rg0 = (size_t)sc * SC_ROWS;
            #pragma unroll 1
            for (int i = tid; i < SC_ROWS * 25; i += NTHREADS) {
                int r = i / 25, p = i - r * 25;
                float2 v = *(const float2*)(x + (rg0 + r) * NIN + 2 * p);
                *(half2*)(smem + X_OFF + swz_off(r, p)) = __float22half2_rn(v);
            }
        }
        __syncthreads();

        // ---- GEMM1 (features on M, rows on N) + relu + in-register pooling ----
        #pragma unroll 1
        for (int s4 = 0; s4 < SEG_PER_W; s4++) {
            const int seg  = wr * SEG_PER_W + s4;
            const int rbase = seg * JP;

            // B fragments: 3 n-tiles (8 x-rows each) x 4 k-steps
            uint32_t b[3][8];
            #pragma unroll
            for (int nt = 0; nt < 3; nt++) {
                const uint32_t rowa = sbase + X_OFF + (uint32_t)(rbase + nt * 8 + nl) * 128;
                const uint32_t a0 = rowa + (((uint32_t)(blk ^ nl)) << 4);
                const uint32_t a1 = rowa + (((uint32_t)((blk + 4) ^ nl)) << 4);
                asm volatile("ldmatrix.sync.aligned.m8n8.x4.shared.b16 {%0,%1,%2,%3}, [%4];"
                             : "=r"(b[nt][0]), "=r"(b[nt][1]), "=r"(b[nt][2]), "=r"(b[nt][3])
                             : "r"(a0));
                asm volatile("ldmatrix.sync.aligned.m8n8.x4.shared.b16 {%0,%1,%2,%3}, [%4];"
                             : "=r"(b[nt][4]), "=r"(b[nt][5]), "=r"(b[nt][6]), "=r"(b[nt][7])
                             : "r"(a1));
            }

            #pragma unroll 1
            for (int fi = 0; fi < FT_PER_W; fi++) {
                const int F = (wc * FT_PER_W + fi) * 16;

                // A fragments: W1 ftile [16 features x 64 k]
                uint32_t a[4][4];
                #pragma unroll
                for (int ks = 0; ks < 4; ks++) {
                    const uint32_t addr = sbase + W1_OFF + (uint32_t)(F + rrA) * 128
                                        + (((uint32_t)((2 * ks + chi) ^ (rrA & 7))) << 4);
                    asm volatile("ldmatrix.sync.aligned.m8n8.x4.shared.b16 {%0,%1,%2,%3}, [%4];"
                                 : "=r"(a[ks][0]), "=r"(a[ks][1]), "=r"(a[ks][2]), "=r"(a[ks][3])
                                 : "r"(addr));
                }

                float pLo = 0.f, pHi = 0.f;
                #pragma unroll
                for (int nt = 0; nt < 3; nt++) {
                    float c0 = 0.f, c1 = 0.f, c2 = 0.f, c3 = 0.f;
                    #pragma unroll
                    for (int ks = 0; ks < 4; ks++) {
                        asm volatile(
                            "mma.sync.aligned.m16n8k16.row.col.f32.f16.f16.f32 "
                            "{%0,%1,%2,%3}, {%4,%5,%6,%7}, {%8,%9}, {%0,%1,%2,%3};"
                            : "+f"(c0), "+f"(c1), "+f"(c2), "+f"(c3)
                            : "r"(a[ks][0]), "r"(a[ks][1]), "r"(a[ks][2]), "r"(a[ks][3]),
                              "r"(b[nt][2 * ks]), "r"(b[nt][2 * ks + 1]));
                    }
                    pLo += fmaxf(c0, 0.f) + fmaxf(c1, 0.f);
                    pHi += fmaxf(c2, 0.f) + fmaxf(c3, 0.f);
                }

                // reduce over the 4 col-pair lanes (bits 0,1) -> full 24-row pool
                pLo += __shfl_xor_sync(0xffffffffu, pLo, 1);
                pLo += __shfl_xor_sync(0xffffffffu, pLo, 2);
                pHi += __shfl_xor_sync(0xffffffffu, pHi, 1);
                pHi += __shfl_xor_sync(0xffffffffu, pHi, 2);

                if (tig == 0) {
                    feat[seg * KFEAT + F + g]     = pLo;
                    feat[seg * KFEAT + F + 8 + g] = pHi;
                }
            }
        }
        __syncthreads();   // all pooled features in feat

        // ---- fused GEMM2: 160 outputs (16 segs x 10 classes) ----
        if (tid < SEGS * CC) {
            const int seg = tid / CC;
            const int c   = tid - seg * CC;
            const float4* f4 = (const float4*)(feat + seg * KFEAT);
            const float4* g4 = (const float4*)(w2s + c * KFEAT);
            float acc = 0.0f;
            #pragma unroll 4
            for (int k = 0; k < KFEAT / 4; k++) {
                float4 fa = f4[k], gb = g4[k];
                acc = fmaf(fa.x, gb.x, acc);
                acc = fmaf(fa.y, gb.y, acc);
                acc = fmaf(fa.z, gb.z, acc);
                acc = fmaf(fa.w, gb.w, acc);
            }
            out[(size_t)(sc * SEGS + seg) * CC + c] = acc * (1.0f / (float)JP);
        }
        // loop-top __syncthreads covers feat/X reuse
    }
}

extern "C" void kernel_launch(void* const* d_in, const int* in_sizes, int n_in,
                              void* d_out, int out_size)
{
    const float* x  = (const float*)d_in[0];
    const float* W1 = (const float*)d_in[1];
    const float* W2 = (const float*)d_in[2];
    float* out = (float*)d_out;

    cudaFuncSetAttribute(classifier_mma2_kernel,
                         cudaFuncAttributeMaxDynamicSharedMemorySize, SMEM_TOTAL);
    classifier_mma2_kernel<<<GRID, NTHREADS, SMEM_TOTAL>>>(x, W1, W2, out);
}

// round 6
// speedup vs baseline: 4.8447x; 1.3814x over previous
#include <cuda_runtime.h>
#include <cuda_fp16.h>
#include <cstdint>

// ---------------- problem constants ----------------
#define T_ROWS   786432
#define NIN      50          // GEMM1 reduction dim (padded to 64 in smem)
#define KFEAT    400         // hidden features = 25 m16 feature-tiles
#define CC       10          // classes
#define JP       24          // pooling window = 3 n8-tiles
#define SC_ROWS  384         // superchunk rows = 16 segments
#define SEGS     16
#define NSC      (T_ROWS / SC_ROWS)      // 2048
#define NTHREADS 640
#define FT_PER_W 5           // 25 ftiles / 5 groups
#define GRID     152

// ---------------- smem layout (bytes) ----------------
#define X_OFF      0
#define X_BYTES    (SC_ROWS * 128)           // 49152  fp16 swizzled
#define W1_OFF     (X_OFF + X_BYTES)
#define W1_BYTES   (KFEAT * 128)             // 51200  fp16 swizzled
#define FEAT_OFF   (W1_OFF + W1_BYTES)
#define FEAT_BYTES (SEGS * KFEAT * 4)        // 25600
#define W2_OFF     (FEAT_OFF + FEAT_BYTES)
#define W2_BYTES   (CC * KFEAT * 4)          // 16000
#define STAGE_OFF  (W2_OFF + W2_BYTES)
#define STAGE_BYTES (SC_ROWS * NIN * 4)      // 76800  fp32 raw x staging
#define SMEM_TOTAL (STAGE_OFF + STAGE_BYTES) // 218752

__device__ __forceinline__ uint32_t smem_u32(const void* p) {
    uint32_t a;
    asm("{ .reg .u64 t; cvta.to.shared.u64 t, %1; cvt.u32.u64 %0, t; }" : "=r"(a) : "l"(p));
    return a;
}
__device__ __forceinline__ void cp16(uint32_t dst, const void* src) {
    asm volatile("cp.async.cg.shared.global [%0], [%1], 16;" :: "r"(dst), "l"(src));
}
// swizzled byte offset for element (row, k=2*kpair) in a [rows x 64] fp16 tile
__device__ __forceinline__ uint32_t swz_off(int row, int kpair) {
    uint32_t bytecol = (uint32_t)(4 * kpair);
    return (uint32_t)row * 128u + (((bytecol >> 4) ^ (uint32_t)(row & 7)) << 4) + (bytecol & 15u);
}

__global__ void __launch_bounds__(NTHREADS, 1)
classifier_mma3_kernel(const float* __restrict__ x,
                       const float* __restrict__ W1,
                       const float* __restrict__ W2,
                       float* __restrict__ out)
{
    extern __shared__ char smem[];
    float* feat = (float*)(smem + FEAT_OFF);
    float* w2s  = (float*)(smem + W2_OFF);

    const int tid  = threadIdx.x;
    const int wid  = tid >> 5;
    const int lane = tid & 31;
    const uint32_t sbase = smem_u32(smem);
    const uint32_t stage = sbase + STAGE_OFF;

    // ---- zero X & W1 smem (covers K padding 50..63) ----
    for (int i = tid; i < (X_BYTES + W1_BYTES) / 4; i += NTHREADS)
        ((uint32_t*)smem)[i] = 0;
    __syncthreads();

    // ---- load W1 -> smem (fp16, swizzled); W2 -> smem fp32 ----
    for (int i = tid; i < KFEAT * 25; i += NTHREADS) {
        int f = i / 25, p = i - f * 25;
        float2 v = *(const float2*)(W1 + f * NIN + 2 * p);
        *(half2*)(smem + W1_OFF + swz_off(f, p)) = __float22half2_rn(v);
    }
    for (int i = tid; i < CC * KFEAT; i += NTHREADS) w2s[i] = W2[i];

    // ---- prologue: stage x for first superchunk ----
    {
        const char* xg = (const char*)x + (size_t)blockIdx.x * STAGE_BYTES;
        for (int i = tid; i < STAGE_BYTES / 16; i += NTHREADS)
            cp16(stage + i * 16, xg + i * 16);
        asm volatile("cp.async.commit_group;" ::: "memory");
        asm volatile("cp.async.wait_group 0;" ::: "memory");
    }
    __syncthreads();

    // ---- per-lane invariants ----
    const int rrA = lane & 15;          // A (W1) row within ftile
    const int chi = lane >> 4;          // A chunk-half selector
    const int nl  = lane & 7;           // B (x) row-in-ntile
    const int blk = lane >> 3;          // B chunk index
    const int g   = lane >> 2;          // feature row-group
    const int tig = lane & 3;
    const int wr  = wid / 5;            // seg-group 0..3
    const int wc  = wid - wr * 5;       // ftile-group 0..4

    for (int sc = blockIdx.x; sc < NSC; sc += GRID) {
        // ---- convert staging (fp32) -> X smem (fp16, swizzled) ----
        #pragma unroll 1
        for (int i = tid; i < SC_ROWS * 25; i += NTHREADS) {
            int r = i / 25, p = i - r * 25;
            float2 v = *(const float2*)(smem + STAGE_OFF + r * 200 + 8 * p);
            *(half2*)(smem + X_OFF + swz_off(r, p)) = __float22half2_rn(v);
        }
        __syncthreads();   // staging reads + X writes complete

        // ---- stream next superchunk's x into staging (overlaps compute) ----
        {
            const int nsc = sc + GRID;
            if (nsc < NSC) {
                const char* xg = (const char*)x + (size_t)nsc * STAGE_BYTES;
                #pragma unroll 1
                for (int i = tid; i < STAGE_BYTES / 16; i += NTHREADS)
                    cp16(stage + i * 16, xg + i * 16);
            }
            asm volatile("cp.async.commit_group;" ::: "memory");
        }

        // ---- GEMM1 (features on M, rows on N) + relu + in-register pooling ----
        #pragma unroll 1
        for (int sp = 0; sp < 2; sp++) {
            const int s0 = wr * 4 + 2 * sp;     // this warp's segment pair

            // B fragments for 2 segments x 3 n-tiles x 4 k-steps (48 regs)
            uint32_t b[2][3][8];
            #pragma unroll
            for (int ss = 0; ss < 2; ss++) {
                #pragma unroll
                for (int nt = 0; nt < 3; nt++) {
                    const uint32_t rowa = sbase + X_OFF
                        + (uint32_t)((s0 + ss) * JP + nt * 8 + nl) * 128;
                    const uint32_t a0 = rowa + (((uint32_t)(blk ^ nl)) << 4);
                    const uint32_t a1 = rowa + (((uint32_t)((blk + 4) ^ nl)) << 4);
                    asm volatile("ldmatrix.sync.aligned.m8n8.x4.shared.b16 {%0,%1,%2,%3}, [%4];"
                                 : "=r"(b[ss][nt][0]), "=r"(b[ss][nt][1]),
                                   "=r"(b[ss][nt][2]), "=r"(b[ss][nt][3]) : "r"(a0));
                    asm volatile("ldmatrix.sync.aligned.m8n8.x4.shared.b16 {%0,%1,%2,%3}, [%4];"
                                 : "=r"(b[ss][nt][4]), "=r"(b[ss][nt][5]),
                                   "=r"(b[ss][nt][6]), "=r"(b[ss][nt][7]) : "r"(a1));
                }
            }

            #pragma unroll 1
            for (int fi = 0; fi < FT_PER_W; fi++) {
                const int F = (wc * FT_PER_W + fi) * 16;

                uint32_t a[4][4];
                #pragma unroll
                for (int ks = 0; ks < 4; ks++) {
                    const uint32_t addr = sbase + W1_OFF + (uint32_t)(F + rrA) * 128
                                        + (((uint32_t)((2 * ks + chi) ^ (rrA & 7))) << 4);
                    asm volatile("ldmatrix.sync.aligned.m8n8.x4.shared.b16 {%0,%1,%2,%3}, [%4];"
                                 : "=r"(a[ks][0]), "=r"(a[ks][1]),
                                   "=r"(a[ks][2]), "=r"(a[ks][3]) : "r"(addr));
                }

                float pLo0 = 0.f, pHi0 = 0.f, pLo1 = 0.f, pHi1 = 0.f;
                #pragma unroll
                for (int nt = 0; nt < 3; nt++) {
                    float c0 = 0.f, c1 = 0.f, c2 = 0.f, c3 = 0.f;
                    float d0 = 0.f, d1 = 0.f, d2 = 0.f, d3 = 0.f;
                    #pragma unroll
                    for (int ks = 0; ks < 4; ks++) {
                        asm volatile(
                            "mma.sync.aligned.m16n8k16.row.col.f32.f16.f16.f32 "
                            "{%0,%1,%2,%3}, {%4,%5,%6,%7}, {%8,%9}, {%0,%1,%2,%3};"
                            : "+f"(c0), "+f"(c1), "+f"(c2), "+f"(c3)
                            : "r"(a[ks][0]), "r"(a[ks][1]), "r"(a[ks][2]), "r"(a[ks][3]),
                              "r"(b[0][nt][2 * ks]), "r"(b[0][nt][2 * ks + 1]));
                        asm volatile(
                            "mma.sync.aligned.m16n8k16.row.col.f32.f16.f16.f32 "
                            "{%0,%1,%2,%3}, {%4,%5,%6,%7}, {%8,%9}, {%0,%1,%2,%3};"
                            : "+f"(d0), "+f"(d1), "+f"(d2), "+f"(d3)
                            : "r"(a[ks][0]), "r"(a[ks][1]), "r"(a[ks][2]), "r"(a[ks][3]),
                              "r"(b[1][nt][2 * ks]), "r"(b[1][nt][2 * ks + 1]));
                    }
                    pLo0 += fmaxf(c0, 0.f) + fmaxf(c1, 0.f);
                    pHi0 += fmaxf(c2, 0.f) + fmaxf(c3, 0.f);
                    pLo1 += fmaxf(d0, 0.f) + fmaxf(d1, 0.f);
                    pHi1 += fmaxf(d2, 0.f) + fmaxf(d3, 0.f);
                }

                // reduce over the 4 col-pair lanes (bits 0,1): completes 24-row pool
                pLo0 += __shfl_xor_sync(0xffffffffu, pLo0, 1);
                pHi0 += __shfl_xor_sync(0xffffffffu, pHi0, 1);
                pLo1 += __shfl_xor_sync(0xffffffffu, pLo1, 1);
                pHi1 += __shfl_xor_sync(0xffffffffu, pHi1, 1);
                pLo0 += __shfl_xor_sync(0xffffffffu, pLo0, 2);
                pHi0 += __shfl_xor_sync(0xffffffffu, pHi0, 2);
                pLo1 += __shfl_xor_sync(0xffffffffu, pLo1, 2);
                pHi1 += __shfl_xor_sync(0xffffffffu, pHi1, 2);

                if (tig == 0) {
                    feat[s0 * KFEAT + F + g]           = pLo0;
                    feat[s0 * KFEAT + F + 8 + g]       = pHi0;
                    feat[(s0 + 1) * KFEAT + F + g]     = pLo1;
                    feat[(s0 + 1) * KFEAT + F + 8 + g] = pHi1;
                }
            }
        }
        __syncthreads();   // all pooled features in feat

        // ---- fused GEMM2: 160 outputs (16 segs x 10 classes) ----
        if (tid < SEGS * CC) {
            const int seg = tid / CC;
            const int c   = tid - seg * CC;
            const float4* f4 = (const float4*)(feat + seg * KFEAT);
            const float4* g4 = (const float4*)(w2s + c * KFEAT);
            float acc = 0.0f;
            #pragma unroll 4
            for (int k = 0; k < KFEAT / 4; k++) {
                float4 fa = f4[k], gb = g4[k];
                acc = fmaf(fa.x, gb.x, acc);
                acc = fmaf(fa.y, gb.y, acc);
                acc = fmaf(fa.z, gb.z, acc);
                acc = fmaf(fa.w, gb.w, acc);
            }
            out[(size_t)(sc * SEGS + seg) * CC + c] = acc * (1.0f / (float)JP);
        }

        asm volatile("cp.async.wait_group 0;" ::: "memory");
        __syncthreads();   // staging full; feat readers done
    }
}

extern "C" void kernel_launch(void* const* d_in, const int* in_sizes, int n_in,
                              void* d_out, int out_size)
{
    const float* x  = (const float*)d_in[0];
    const float* W1 = (const float*)d_in[1];
    const float* W2 = (const float*)d_in[2];
    float* out = (float*)d_out;

    cudaFuncSetAttribute(classifier_mma3_kernel,
                         cudaFuncAttributeMaxDynamicSharedMemorySize, SMEM_TOTAL);
    classifier_mma3_kernel<<<GRID, NTHREADS, SMEM_TOTAL>>>(x, W1, W2, out);
}

// round 10
// speedup vs baseline: 6.2838x; 1.2970x over previous
#include <cuda_runtime.h>
#include <cuda_fp16.h>
#include <cstdint>

// ---------------- problem constants ----------------
#define T_ROWS   786432
#define NIN      50          // GEMM1 reduction dim (padded to 64 in smem)
#define KFEAT    400         // hidden features = 25 m16 feature-tiles
#define CC       10          // classes
#define JP       24          // pooling window = 3 n8-tiles
#define SC_ROWS  384         // superchunk rows = 16 segments
#define SEGS     16
#define NSC      (T_ROWS / SC_ROWS)      // 2048
#define NTHREADS 640
#define FT_PER_W 5           // 25 ftiles / 5 groups
#define GRID     152
#define KS2      25          // GEMM2 k16 steps (400/16)

// ---------------- smem layout (bytes) ----------------
#define X_OFF      0
#define X_BYTES    (SC_ROWS * 128)           // 49152  fp16 swizzled
#define W1_OFF     (X_OFF + X_BYTES)
#define W1_BYTES   (KFEAT * 128)             // 51200  fp16 swizzled
#define F16_OFF    (W1_OFF + W1_BYTES)
#define F16_STRIDE 816                       // 408 halfs; 51 chunks, conflict-free
#define F16_BYTES  (SEGS * F16_STRIDE)       // 13056
#define W2F_OFF    (F16_OFF + F16_BYTES)
#define W2F_BYTES  (2 * KS2 * 2 * 32 * 4)    // 12800  pre-packed B frags
#define STAGE_OFF  (W2F_OFF + W2F_BYTES)
#define STAGE_BYTES (SC_ROWS * NIN * 4)      // 76800  fp32 raw x staging
#define SMEM_TOTAL (STAGE_OFF + STAGE_BYTES) // 203008

__device__ __forceinline__ uint32_t smem_u32(const void* p) {
    uint32_t a;
    asm("{ .reg .u64 t; cvta.to.shared.u64 t, %1; cvt.u32.u64 %0, t; }" : "=r"(a) : "l"(p));
    return a;
}
__device__ __forceinline__ void cp16(uint32_t dst, const void* src) {
    asm volatile("cp.async.cg.shared.global [%0], [%1], 16;" :: "r"(dst), "l"(src));
}
// swizzled byte offset for element (row, k=2*kpair) in a [rows x 64] fp16 tile
__device__ __forceinline__ uint32_t swz_off(int row, int kpair) {
    uint32_t bytecol = (uint32_t)(4 * kpair);
    return (uint32_t)row * 128u + (((bytecol >> 4) ^ (uint32_t)(row & 7)) << 4) + (bytecol & 15u);
}

__global__ void __launch_bounds__(NTHREADS, 1)
classifier_mma4_kernel(const float* __restrict__ x,
                       const float* __restrict__ W1,
                       const float* __restrict__ W2,
                       float* __restrict__ out)
{
    extern __shared__ char smem[];

    const int tid  = threadIdx.x;
    const int wid  = tid >> 5;
    const int lane = tid & 31;
    const uint32_t sbase = smem_u32(smem);
    const uint32_t stage = sbase + STAGE_OFF;

    // ---- zero X & W1 smem (covers K padding 50..63) ----
    for (int i = tid; i < (X_BYTES + W1_BYTES) / 4; i += NTHREADS)
        ((uint32_t*)smem)[i] = 0;
    __syncthreads();

    // ---- load W1 -> smem (fp16, swizzled) ----
    for (int i = tid; i < KFEAT * 25; i += NTHREADS) {
        int f = i / 25, p = i - f * 25;
        float2 v = *(const float2*)(W1 + f * NIN + 2 * p);
        *(half2*)(smem + W1_OFF + swz_off(f, p)) = __float22half2_rn(v);
    }

    // ---- pre-pack W2 into B-fragment order (fp16), warps 0 & 1 ----
    if (wid < 2) {
        const int n = wid * 8 + (lane >> 2);
        #pragma unroll 1
        for (int ks = 0; ks < KS2; ks++) {
            #pragma unroll
            for (int r = 0; r < 2; r++) {
                const int k = ks * 16 + (lane & 3) * 2 + r * 8;
                float lo = 0.f, hi = 0.f;
                if (n < CC) { lo = W2[n * KFEAT + k]; hi = W2[n * KFEAT + k + 1]; }
                half2 h = __floats2half2_rn(lo, hi);
                ((uint32_t*)(smem + W2F_OFF))[((wid * KS2 + ks) * 2 + r) * 32 + lane] =
                    *(uint32_t*)&h;
            }
        }
    }

    // ---- prologue: stage x for first superchunk ----
    {
        const char* xg = (const char*)x + (size_t)blockIdx.x * STAGE_BYTES;
        for (int i = tid; i < STAGE_BYTES / 16; i += NTHREADS)
            cp16(stage + i * 16, xg + i * 16);
        asm volatile("cp.async.commit_group;" ::: "memory");
        asm volatile("cp.async.wait_group 0;" ::: "memory");
    }
    __syncthreads();

    // ---- per-lane invariants ----
    const int rrA = lane & 15;          // A (W1) row within ftile
    const int chi = lane >> 4;          // A chunk-half selector
    const int nl  = lane & 7;           // B (x) row-in-ntile
    const int blk = lane >> 3;          // B chunk index
    const int g   = lane >> 2;          // feature row-group
    const int tig = lane & 3;
    const int wr  = wid / 5;            // seg-group 0..3
    const int wc  = wid - wr * 5;       // ftile-group 0..4

    for (int sc = blockIdx.x; sc < NSC; sc += GRID) {
        // ---- convert staging (fp32) -> X smem (fp16, swizzled) ----
        #pragma unroll 1
        for (int i = tid; i < SC_ROWS * 25; i += NTHREADS) {
            int r = i / 25, p = i - r * 25;
            float2 v = *(const float2*)(smem + STAGE_OFF + r * 200 + 8 * p);
            *(half2*)(smem + X_OFF + swz_off(r, p)) = __float22half2_rn(v);
        }
        __syncthreads();   // staging reads + X writes complete

        // ---- stream next superchunk's x into staging (overlaps compute) ----
        {
            const int nsc = sc + GRID;
            if (nsc < NSC) {
                const char* xg = (const char*)x + (size_t)nsc * STAGE_BYTES;
                #pragma unroll 1
                for (int i = tid; i < STAGE_BYTES / 16; i += NTHREADS)
                    cp16(stage + i * 16, xg + i * 16);
            }
            asm volatile("cp.async.commit_group;" ::: "memory");
        }

        // ---- GEMM1 (features on M, rows on N) + relu + in-register pooling ----
        #pragma unroll 1
        for (int sp = 0; sp < 2; sp++) {
            const int s0 = wr * 4 + 2 * sp;     // this warp's segment pair

            // B fragments for 2 segments x 3 n-tiles x 4 k-steps (48 regs)
            uint32_t b[2][3][8];
            #pragma unroll
            for (int ss = 0; ss < 2; ss++) {
                #pragma unroll
                for (int nt = 0; nt < 3; nt++) {
                    const uint32_t rowa = sbase + X_OFF
                        + (uint32_t)((s0 + ss) * JP + nt * 8 + nl) * 128;
                    const uint32_t a0 = rowa + (((uint32_t)(blk ^ nl)) << 4);
                    const uint32_t a1 = rowa + (((uint32_t)((blk + 4) ^ nl)) << 4);
                    asm volatile("ldmatrix.sync.aligned.m8n8.x4.shared.b16 {%0,%1,%2,%3}, [%4];"
                                 : "=r"(b[ss][nt][0]), "=r"(b[ss][nt][1]),
                                   "=r"(b[ss][nt][2]), "=r"(b[ss][nt][3]) : "r"(a0));
                    asm volatile("ldmatrix.sync.aligned.m8n8.x4.shared.b16 {%0,%1,%2,%3}, [%4];"
                                 : "=r"(b[ss][nt][4]), "=r"(b[ss][nt][5]),
                                   "=r"(b[ss][nt][6]), "=r"(b[ss][nt][7]) : "r"(a1));
                }
            }

            #pragma unroll 1
            for (int fi = 0; fi < FT_PER_W; fi++) {
                const int F = (wc * FT_PER_W + fi) * 16;

                uint32_t a[4][4];
                #pragma unroll
                for (int ks = 0; ks < 4; ks++) {
                    const uint32_t addr = sbase + W1_OFF + (uint32_t)(F + rrA) * 128
                                        + (((uint32_t)((2 * ks + chi) ^ (rrA & 7))) << 4);
                    asm volatile("ldmatrix.sync.aligned.m8n8.x4.shared.b16 {%0,%1,%2,%3}, [%4];"
                                 : "=r"(a[ks][0]), "=r"(a[ks][1]),
                                   "=r"(a[ks][2]), "=r"(a[ks][3]) : "r"(addr));
                }

                float pLo0 = 0.f, pHi0 = 0.f, pLo1 = 0.f, pHi1 = 0.f;
                #pragma unroll
                for (int nt = 0; nt < 3; nt++) {
                    float c0 = 0.f, c1 = 0.f, c2 = 0.f, c3 = 0.f;
                    float d0 = 0.f, d1 = 0.f, d2 = 0.f, d3 = 0.f;
                    #pragma unroll
                    for (int ks = 0; ks < 4; ks++) {
                        asm volatile(
                            "mma.sync.aligned.m16n8k16.row.col.f32.f16.f16.f32 "
                            "{%0,%1,%2,%3}, {%4,%5,%6,%7}, {%8,%9}, {%0,%1,%2,%3};"
                            : "+f"(c0), "+f"(c1), "+f"(c2), "+f"(c3)
                            : "r"(a[ks][0]), "r"(a[ks][1]), "r"(a[ks][2]), "r"(a[ks][3]),
                              "r"(b[0][nt][2 * ks]), "r"(b[0][nt][2 * ks + 1]));
                        asm volatile(
                            "mma.sync.aligned.m16n8k16.row.col.f32.f16.f16.f32 "
                            "{%0,%1,%2,%3}, {%4,%5,%6,%7}, {%8,%9}, {%0,%1,%2,%3};"
                            : "+f"(d0), "+f"(d1), "+f"(d2), "+f"(d3)
                            : "r"(a[ks][0]), "r"(a[ks][1]), "r"(a[ks][2]), "r"(a[ks][3]),
                              "r"(b[1][nt][2 * ks]), "r"(b[1][nt][2 * ks + 1]));
                    }
                    pLo0 += fmaxf(c0, 0.f) + fmaxf(c1, 0.f);
                    pHi0 += fmaxf(c2, 0.f) + fmaxf(c3, 0.f);
                    pLo1 += fmaxf(d0, 0.f) + fmaxf(d1, 0.f);
                    pHi1 += fmaxf(d2, 0.f) + fmaxf(d3, 0.f);
                }

                // reduce over the 4 col-pair lanes: completes 24-row pool
                pLo0 += __shfl_xor_sync(0xffffffffu, pLo0, 1);
                pHi0 += __shfl_xor_sync(0xffffffffu, pHi0, 1);
                pLo1 += __shfl_xor_sync(0xffffffffu, pLo1, 1);
                pHi1 += __shfl_xor_sync(0xffffffffu, pHi1, 1);
                pLo0 += __shfl_xor_sync(0xffffffffu, pLo0, 2);
                pHi0 += __shfl_xor_sync(0xffffffffu, pHi0, 2);
                pLo1 += __shfl_xor_sync(0xffffffffu, pLo1, 2);
                pHi1 += __shfl_xor_sync(0xffffffffu, pHi1, 2);

                // every lane stores one fp16 pooled feature (scaled by 1/24)
                {
                    float v = (tig == 0) ? pLo0 : (tig == 1) ? pHi0
                            : (tig == 2) ? pLo1 : pHi1;
                    const int seg = s0 + (tig >> 1);
                    const int f   = F + g + ((tig & 1) << 3);
                    *(half*)(smem + F16_OFF + seg * F16_STRIDE + f * 2) =
                        __float2half(v * (1.0f / (float)JP));
                }
            }
        }
        __syncthreads();   // all pooled features in feat16

        // ---- GEMM2 via MMA: warps 0,1 (n-tiles 0,1) ----
        if (wid < 2) {
            float e0 = 0.f, e1 = 0.f, e2 = 0.f, e3 = 0.f;
            const uint32_t arow = sbase + F16_OFF + (uint32_t)(lane & 15) * F16_STRIDE
                                + (uint32_t)(lane >> 4) * 16;
            const uint32_t* w2f = (const uint32_t*)(smem + W2F_OFF) + (wid * KS2 * 2) * 32 + lane;
            #pragma unroll 5
            for (int ks = 0; ks < KS2; ks++) {
                uint32_t a0, a1, a2, a3;
                asm volatile("ldmatrix.sync.aligned.m8n8.x4.shared.b16 {%0,%1,%2,%3}, [%4];"
                             : "=r"(a0), "=r"(a1), "=r"(a2), "=r"(a3)
                             : "r"(arow + ks * 32));
                const uint32_t b0 = w2f[(ks * 2) * 32];
                const uint32_t b1 = w2f[(ks * 2 + 1) * 32];
                asm volatile(
                    "mma.sync.aligned.m16n8k16.row.col.f32.f16.f16.f32 "
                    "{%0,%1,%2,%3}, {%4,%5,%6,%7}, {%8,%9}, {%0,%1,%2,%3};"
                    : "+f"(e0), "+f"(e1), "+f"(e2), "+f"(e3)
                    : "r"(a0), "r"(a1), "r"(a2), "r"(a3), "r"(b0), "r"(b1));
            }
            const int n = wid * 8 + 2 * (lane & 3);
            if (n < CC) {
                const int r0 = lane >> 2;
                float2 v0 = {e0, e1}, v1 = {e2, e3};
                *(float2*)(out + (size_t)(sc * SEGS + r0) * CC + n)     = v0;
                *(float2*)(out + (size_t)(sc * SEGS + r0 + 8) * CC + n) = v1;
            }
        }

        asm volatile("cp.async.wait_group 0;" ::: "memory");
        __syncthreads();   // staging full; feat16 readers done
    }
}

extern "C" void kernel_launch(void* const* d_in, const int* in_sizes, int n_in,
                              void* d_out, int out_size)
{
    const float* x  = (const float*)d_in[0];
    const float* W1 = (const float*)d_in[1];
    const float* W2 = (const float*)d_in[2];
    float* out = (float*)d_out;

    cudaFuncSetAttribute(classifier_mma4_kernel,
                         cudaFuncAttributeMaxDynamicSharedMemorySize, SMEM_TOTAL);
    classifier_mma4_kernel<<<GRID, NTHREADS, SMEM_TOTAL>>>(x, W1, W2, out);
}

// round 11
// speedup vs baseline: 6.9905x; 1.1125x over previous
#include <cuda_runtime.h>
#include <cuda_fp16.h>
#include <cstdint>

// ---------------- problem constants ----------------
#define T_ROWS   786432
#define NIN      50          // GEMM1 reduction dim (padded to 64 in smem)
#define KFEAT    400         // hidden features = 25 m16 feature-tiles
#define CC       10          // classes
#define JP       24          // pooling window = 3 n8-tiles
#define SC_ROWS  384         // superchunk rows = 16 segments
#define SEGS     16
#define NSC      (T_ROWS / SC_ROWS)      // 2048
#define NTHREADS 640
#define FT_PER_W 5           // 25 ftiles / 5 groups
#define GRID     152
#define KS2      25          // GEMM2 k16 steps (400/16)

// ---------------- smem layout (bytes) ----------------
#define X_OFF      0
#define X_BYTES    (SC_ROWS * 128)           // 49152  fp16 swizzled
#define W1_OFF     (X_OFF + X_BYTES)
#define W1_BYTES   (KFEAT * 128)             // 51200  fp16 swizzled
#define F16_OFF    (W1_OFF + W1_BYTES)
#define F16_STRIDE 816                       // 408 halfs; 51 chunks, conflict-free
#define F16_BYTES  (SEGS * F16_STRIDE)       // 13056
#define W2F_OFF    (F16_OFF + F16_BYTES)
#define W2F_BYTES  (2 * KS2 * 2 * 32 * 4)    // 12800  pre-packed B frags
#define STAGE_OFF  (W2F_OFF + W2F_BYTES)
#define STAGE_BYTES (SC_ROWS * NIN * 4)      // 76800  fp32 raw x staging
#define SMEM_TOTAL (STAGE_OFF + STAGE_BYTES) // 203008

__device__ __forceinline__ uint32_t smem_u32(const void* p) {
    uint32_t a;
    asm("{ .reg .u64 t; cvta.to.shared.u64 t, %1; cvt.u32.u64 %0, t; }" : "=r"(a) : "l"(p));
    return a;
}
__device__ __forceinline__ void cp16(uint32_t dst, const void* src) {
    asm volatile("cp.async.cg.shared.global [%0], [%1], 16;" :: "r"(dst), "l"(src));
}
// swizzled byte offset for element (row, k=2*kpair) in a [rows x 64] fp16 tile
__device__ __forceinline__ uint32_t swz_off(int row, int kpair) {
    uint32_t bytecol = (uint32_t)(4 * kpair);
    return (uint32_t)row * 128u + (((bytecol >> 4) ^ (uint32_t)(row & 7)) << 4) + (bytecol & 15u);
}

__global__ void __launch_bounds__(NTHREADS, 1)
classifier_mma5_kernel(const float* __restrict__ x,
                       const float* __restrict__ W1,
                       const float* __restrict__ W2,
                       float* __restrict__ out)
{
    extern __shared__ char smem[];

    const int tid  = threadIdx.x;
    const int wid  = tid >> 5;
    const int lane = tid & 31;
    const uint32_t sbase = smem_u32(smem);
    const uint32_t stage = sbase + STAGE_OFF;

    // ---- zero X & W1 smem (covers K padding 50..63, persists) ----
    for (int i = tid; i < (X_BYTES + W1_BYTES) / 4; i += NTHREADS)
        ((uint32_t*)smem)[i] = 0;
    __syncthreads();

    // ---- load W1 -> smem (fp16, swizzled) ----
    for (int i = tid; i < KFEAT * 25; i += NTHREADS) {
        int f = i / 25, p = i - f * 25;
        float2 v = *(const float2*)(W1 + f * NIN + 2 * p);
        *(half2*)(smem + W1_OFF + swz_off(f, p)) = __float22half2_rn(v);
    }

    // ---- pre-pack W2 into B-fragment order (fp16), warps 0 & 1 ----
    if (wid < 2) {
        const int n = wid * 8 + (lane >> 2);
        #pragma unroll 1
        for (int ks = 0; ks < KS2; ks++) {
            #pragma unroll
            for (int r = 0; r < 2; r++) {
                const int k = ks * 16 + (lane & 3) * 2 + r * 8;
                float lo = 0.f, hi = 0.f;
                if (n < CC) { lo = W2[n * KFEAT + k]; hi = W2[n * KFEAT + k + 1]; }
                half2 h = __floats2half2_rn(lo, hi);
                ((uint32_t*)(smem + W2F_OFF))[((wid * KS2 + ks) * 2 + r) * 32 + lane] =
                    *(uint32_t*)&h;
            }
        }
    }

    // ---- prologue: stage x for first superchunk ----
    {
        const char* xg = (const char*)x + (size_t)blockIdx.x * STAGE_BYTES;
        for (int i = tid; i < STAGE_BYTES / 16; i += NTHREADS)
            cp16(stage + i * 16, xg + i * 16);
        asm volatile("cp.async.commit_group;" ::: "memory");
        asm volatile("cp.async.wait_group 0;" ::: "memory");
    }
    __syncthreads();

    // ---- per-lane invariants ----
    const int rrA = lane & 15;          // A (W1) row within ftile
    const int chi = lane >> 4;          // A chunk-half selector
    const int nl  = lane & 7;           // B (x) row-in-ntile
    const int blk = lane >> 3;          // B chunk index (x4 load)
    const int bl2 = (lane >> 3) & 1;    // B chunk sub-index (x2 load)
    const int g   = lane >> 2;          // feature row-group
    const int tig = lane & 3;
    const int wr  = wid / 5;            // seg-group 0..3
    const int wc  = wid - wr * 5;       // ftile-group 0..4

    int prev_sc = -1;

    for (int sc = blockIdx.x; sc < NSC; sc += GRID) {
        // ---- phase (a): warps 2..19 convert staging->X ; warps 0,1 GEMM2(prev) ----
        if (wid >= 2) {
            #pragma unroll 1
            for (int i = tid - 64; i < SC_ROWS * 25; i += NTHREADS - 64) {
                int r = i / 25, p = i - r * 25;
                float2 v = *(const float2*)(smem + STAGE_OFF + r * 200 + 8 * p);
                *(half2*)(smem + X_OFF + swz_off(r, p)) = __float22half2_rn(v);
            }
        } else if (prev_sc >= 0) {
            float e0 = 0.f, e1 = 0.f, e2 = 0.f, e3 = 0.f;
            const uint32_t arow = sbase + F16_OFF + (uint32_t)(lane & 15) * F16_STRIDE
                                + (uint32_t)(lane >> 4) * 16;
            const uint32_t* w2f = (const uint32_t*)(smem + W2F_OFF) + (wid * KS2 * 2) * 32 + lane;
            #pragma unroll 5
            for (int ks = 0; ks < KS2; ks++) {
                uint32_t a0, a1, a2, a3;
                asm volatile("ldmatrix.sync.aligned.m8n8.x4.shared.b16 {%0,%1,%2,%3}, [%4];"
                             : "=r"(a0), "=r"(a1), "=r"(a2), "=r"(a3)
                             : "r"(arow + ks * 32));
                const uint32_t b0 = w2f[(ks * 2) * 32];
                const uint32_t b1 = w2f[(ks * 2 + 1) * 32];
                asm volatile(
                    "mma.sync.aligned.m16n8k16.row.col.f32.f16.f16.f32 "
                    "{%0,%1,%2,%3}, {%4,%5,%6,%7}, {%8,%9}, {%0,%1,%2,%3};"
                    : "+f"(e0), "+f"(e1), "+f"(e2), "+f"(e3)
                    : "r"(a0), "r"(a1), "r"(a2), "r"(a3), "r"(b0), "r"(b1));
            }
            const int n = wid * 8 + 2 * (lane & 3);
            if (n < CC) {
                const int r0 = lane >> 2;
                float2 v0 = {e0, e1}, v1 = {e2, e3};
                *(float2*)(out + (size_t)(prev_sc * SEGS + r0) * CC + n)     = v0;
                *(float2*)(out + (size_t)(prev_sc * SEGS + r0 + 8) * CC + n) = v1;
            }
        }
        __syncthreads();   // (b) X ready; staging consumed; gemm2(prev) done

        // ---- (c) stream next superchunk's x into staging ----
        {
            const int nsc = sc + GRID;
            if (nsc < NSC) {
                const char* xg = (const char*)x + (size_t)nsc * STAGE_BYTES;
                #pragma unroll 1
                for (int i = tid; i < STAGE_BYTES / 16; i += NTHREADS)
                    cp16(stage + i * 16, xg + i * 16);
            }
            asm volatile("cp.async.commit_group;" ::: "memory");
        }

        // ---- (d) GEMM1 (features on M, rows on N) + relu + in-register pooling ----
        #pragma unroll 1
        for (int sp = 0; sp < 2; sp++) {
            const int s0 = wr * 4 + 2 * sp;     // this warp's segment pair

            // B fragments: 2 segs x 3 n-tiles x (6 k16-pair regs + 1 k8 reg)
            uint32_t b[2][3][7];
            #pragma unroll
            for (int ss = 0; ss < 2; ss++) {
                #pragma unroll
                for (int nt = 0; nt < 3; nt++) {
                    const uint32_t rowa = sbase + X_OFF
                        + (uint32_t)((s0 + ss) * JP + nt * 8 + nl) * 128;
                    const uint32_t a0 = rowa + (((uint32_t)(blk ^ nl)) << 4);        // chunks 0..3
                    const uint32_t a1 = rowa + (((uint32_t)((4 + bl2) ^ nl)) << 4);  // chunks 4,5
                    const uint32_t a2 = rowa + (((uint32_t)(6 ^ nl)) << 4);          // chunk 6
                    asm volatile("ldmatrix.sync.aligned.m8n8.x4.shared.b16 {%0,%1,%2,%3}, [%4];"
                                 : "=r"(b[ss][nt][0]), "=r"(b[ss][nt][1]),
                                   "=r"(b[ss][nt][2]), "=r"(b[ss][nt][3]) : "r"(a0));
                    asm volatile("ldmatrix.sync.aligned.m8n8.x2.shared.b16 {%0,%1}, [%2];"
                                 : "=r"(b[ss][nt][4]), "=r"(b[ss][nt][5]) : "r"(a1));
                    asm volatile("ldmatrix.sync.aligned.m8n8.x1.shared.b16 {%0}, [%1];"
                                 : "=r"(b[ss][nt][6]) : "r"(a2));
                }
            }

            #pragma unroll 1
            for (int fi = 0; fi < FT_PER_W; fi++) {
                const int F = (wc * FT_PER_W + fi) * 16;
                const uint32_t abase = sbase + W1_OFF + (uint32_t)(F + rrA) * 128;

                uint32_t a[3][4];   // k16 steps 0..2
                #pragma unroll
                for (int ks = 0; ks < 3; ks++) {
                    const uint32_t addr = abase + (((uint32_t)((2 * ks + chi) ^ (rrA & 7))) << 4);
                    asm volatile("ldmatrix.sync.aligned.m8n8.x4.shared.b16 {%0,%1,%2,%3}, [%4];"
                                 : "=r"(a[ks][0]), "=r"(a[ks][1]),
                                   "=r"(a[ks][2]), "=r"(a[ks][3]) : "r"(addr));
                }
                uint32_t a8[2];     // k8 step: chunk 6 (k48..55)
                {
                    const uint32_t addr = abase + (((uint32_t)(6 ^ (rrA & 7))) << 4);
                    asm volatile("ldmatrix.sync.aligned.m8n8.x2.shared.b16 {%0,%1}, [%2];"
                                 : "=r"(a8[0]), "=r"(a8[1]) : "r"(addr));
                }

                float pLo0 = 0.f, pHi0 = 0.f, pLo1 = 0.f, pHi1 = 0.f;
                #pragma unroll
                for (int nt = 0; nt < 3; nt++) {
                    float c0 = 0.f, c1 = 0.f, c2 = 0.f, c3 = 0.f;
                    float d0 = 0.f, d1 = 0.f, d2 = 0.f, d3 = 0.f;
                    #pragma unroll
                    for (int ks = 0; ks < 3; ks++) {
                        asm volatile(
                            "mma.sync.aligned.m16n8k16.row.col.f32.f16.f16.f32 "
                            "{%0,%1,%2,%3}, {%4,%5,%6,%7}, {%8,%9}, {%0,%1,%2,%3};"
                            : "+f"(c0), "+f"(c1), "+f"(c2), "+f"(c3)
                            : "r"(a[ks][0]), "r"(a[ks][1]), "r"(a[ks][2]), "r"(a[ks][3]),
                              "r"(b[0][nt][2 * ks]), "r"(b[0][nt][2 * ks + 1]));
                        asm volatile(
                            "mma.sync.aligned.m16n8k16.row.col.f32.f16.f16.f32 "
                            "{%0,%1,%2,%3}, {%4,%5,%6,%7}, {%8,%9}, {%0,%1,%2,%3};"
                            : "+f"(d0), "+f"(d1), "+f"(d2), "+f"(d3)
                            : "r"(a[ks][0]), "r"(a[ks][1]), "r"(a[ks][2]), "r"(a[ks][3]),
                              "r"(b[1][nt][2 * ks]), "r"(b[1][nt][2 * ks + 1]));
                    }
                    // k8 tail: k48..55 (real data k48,49; rest zero-padded)
                    asm volatile(
                        "mma.sync.aligned.m16n8k8.row.col.f32.f16.f16.f32 "
                        "{%0,%1,%2,%3}, {%4,%5}, {%6}, {%0,%1,%2,%3};"
                        : "+f"(c0), "+f"(c1), "+f"(c2), "+f"(c3)
                        : "r"(a8[0]), "r"(a8[1]), "r"(b[0][nt][6]));
                    asm volatile(
                        "mma.sync.aligned.m16n8k8.row.col.f32.f16.f16.f32 "
                        "{%0,%1,%2,%3}, {%4,%5}, {%6}, {%0,%1,%2,%3};"
                        : "+f"(d0), "+f"(d1), "+f"(d2), "+f"(d3)
                        : "r"(a8[0]), "r"(a8[1]), "r"(b[1][nt][6]));

                    pLo0 += fmaxf(c0, 0.f) + fmaxf(c1, 0.f);
                    pHi0 += fmaxf(c2, 0.f) + fmaxf(c3, 0.f);
                    pLo1 += fmaxf(d0, 0.f) + fmaxf(d1, 0.f);
                    pHi1 += fmaxf(d2, 0.f) + fmaxf(d3, 0.f);
                }

                // reduce over the 4 col-pair lanes: completes 24-row pool
                pLo0 += __shfl_xor_sync(0xffffffffu, pLo0, 1);
                pHi0 += __shfl_xor_sync(0xffffffffu, pHi0, 1);
                pLo1 += __shfl_xor_sync(0xffffffffu, pLo1, 1);
                pHi1 += __shfl_xor_sync(0xffffffffu, pHi1, 1);
                pLo0 += __shfl_xor_sync(0xffffffffu, pLo0, 2);
                pHi0 += __shfl_xor_sync(0xffffffffu, pHi0, 2);
                pLo1 += __shfl_xor_sync(0xffffffffu, pLo1, 2);
                pHi1 += __shfl_xor_sync(0xffffffffu, pHi1, 2);

                // every lane stores one fp16 pooled feature (scaled by 1/24)
                {
                    float v = (tig == 0) ? pLo0 : (tig == 1) ? pHi0
                            : (tig == 2) ? pLo1 : pHi1;
                    const int seg = s0 + (tig >> 1);
                    const int f   = F + g + ((tig & 1) << 3);
                    *(half*)(smem + F16_OFF + seg * F16_STRIDE + f * 2) =
                        __float2half(v * (1.0f / (float)JP));
                }
            }
        }

        // ---- (e) staging refilled; feat16 complete ----
        asm volatile("cp.async.wait_group 0;" ::: "memory");
        __syncthreads();
        prev_sc = sc;
    }

    // ---- epilogue GEMM2 for the last superchunk ----
    if (wid < 2 && prev_sc >= 0) {
        float e0 = 0.f, e1 = 0.f, e2 = 0.f, e3 = 0.f;
        const uint32_t arow = sbase + F16_OFF + (uint32_t)(lane & 15) * F16_STRIDE
                            + (uint32_t)(lane >> 4) * 16;
        const uint32_t* w2f = (const uint32_t*)(smem + W2F_OFF) + (wid * KS2 * 2) * 32 + lane;
        #pragma unroll 5
        for (int ks = 0; ks < KS2; ks++) {
            uint32_t a0, a1, a2, a3;
            asm volatile("ldmatrix.sync.aligned.m8n8.x4.shared.b16 {%0,%1,%2,%3}, [%4];"
                         : "=r"(a0), "=r"(a1), "=r"(a2), "=r"(a3)
                         : "r"(arow + ks * 32));
            const uint32_t b0 = w2f[(ks * 2) * 32];
            const uint32_t b1 = w2f[(ks * 2 + 1) * 32];
            asm volatile(
                "mma.sync.aligned.m16n8k16.row.col.f32.f16.f16.f32 "
                "{%0,%1,%2,%3}, {%4,%5,%6,%7}, {%8,%9}, {%0,%1,%2,%3};"
                : "+f"(e0), "+f"(e1), "+f"(e2), "+f"(e3)
                : "r"(a0), "r"(a1), "r"(a2), "r"(a3), "r"(b0), "r"(b1));
        }
        const int n = wid * 8 + 2 * (lane & 3);
        if (n < CC) {
            const int r0 = lane >> 2;
            float2 v0 = {e0, e1}, v1 = {e2, e3};
            *(float2*)(out + (size_t)(prev_sc * SEGS + r0) * CC + n)     = v0;
            *(float2*)(out + (size_t)(prev_sc * SEGS + r0 + 8) * CC + n) = v1;
        }
    }
}

extern "C" void kernel_launch(void* const* d_in, const int* in_sizes, int n_in,
                              void* d_out, int out_size)
{
    const float* x  = (const float*)d_in[0];
    const float* W1 = (const float*)d_in[1];
    const float* W2 = (const float*)d_in[2];
    float* out = (float*)d_out;

    cudaFuncSetAttribute(classifier_mma5_kernel,
                         cudaFuncAttributeMaxDynamicSharedMemorySize, SMEM_TOTAL);
    classifier_mma5_kernel<<<GRID, NTHREADS, SMEM_TOTAL>>>(x, W1, W2, out);
}